// round 2
// baseline (speedup 1.0000x reference)
#include <cuda_runtime.h>

// GraphAttention restructured:
//   A  = relu(srcF@src_w+src_b) @ W1[0:128]                (per src node)
//   C  = relu(dstF@dst_w+dst_b) @ W1[256:384] + b1         (per dst node)
//   per edge e=(s,d): distf = relu(dpos@dist_w + dist_b)
//                     h = relu(A[s] + distf@W1[128:256] + C[d]); H[d] += h; deg[d]++
//   agg = dst_enc + H@W2 + deg*b2 ; T = relu(LN(agg))
//   out = relu(T@out_w + out_b + dstF)

#define S_N 16384
#define D_N 16384
#define F   128
#define PAD 132   // 132 floats = 528B, 16B-aligned rows

__device__ float g_src_enc[S_N * F];
__device__ float g_dst_enc[D_N * F];
__device__ float g_Aproj[S_N * F];
__device__ float g_Cproj[D_N * F];
__device__ float g_H[D_N * F];
__device__ float g_agg[D_N * F];
__device__ float g_T[D_N * F];
__device__ int   g_deg[D_N];

// ---------------- shared-tile helpers ----------------

// A row-major [128 x 128] -> As[k*PAD + row] (transposed, k-major)
__device__ __forceinline__ void load_A_transposed(const float* __restrict__ A,
                                                  float* As, int tid) {
    for (int c = tid; c < 128 * 32; c += 256) {
        int kq = c & 31, row = c >> 5;
        float4 v = *reinterpret_cast<const float4*>(A + (size_t)row * 128 + kq * 4);
        As[(kq * 4 + 0) * PAD + row] = v.x;
        As[(kq * 4 + 1) * PAD + row] = v.y;
        As[(kq * 4 + 2) * PAD + row] = v.z;
        As[(kq * 4 + 3) * PAD + row] = v.w;
    }
}

// B rows [64 x 128] row-major -> Bs[k*PAD + col]
__device__ __forceinline__ void load_B_half(const float* __restrict__ B,
                                            float* Bs, int tid) {
    for (int c = tid; c < 64 * 32; c += 256) {
        int colq = c & 31, k = c >> 5;
        *reinterpret_cast<float4*>(Bs + k * PAD + colq * 4) =
            *reinterpret_cast<const float4*>(B + (size_t)k * 128 + colq * 4);
    }
}

// 64-step K loop: acc[8][8] += As[k][ty*8+i] * Bs[k][tx*8+j]
__device__ __forceinline__ void mma_half(const float* __restrict__ As,
                                         const float* __restrict__ Bs,
                                         float acc[8][8], int ty, int tx) {
#pragma unroll 8
    for (int k = 0; k < 64; k++) {
        float4 a0 = *reinterpret_cast<const float4*>(As + k * PAD + ty * 8);
        float4 a1 = *reinterpret_cast<const float4*>(As + k * PAD + ty * 8 + 4);
        float4 b0 = *reinterpret_cast<const float4*>(Bs + k * PAD + tx * 8);
        float4 b1 = *reinterpret_cast<const float4*>(Bs + k * PAD + tx * 8 + 4);
        float a[8] = {a0.x, a0.y, a0.z, a0.w, a1.x, a1.y, a1.z, a1.w};
        float b[8] = {b0.x, b0.y, b0.z, b0.w, b1.x, b1.y, b1.z, b1.w};
#pragma unroll
        for (int i = 0; i < 8; i++)
#pragma unroll
            for (int j = 0; j < 8; j++)
                acc[i][j] = fmaf(a[i], b[j], acc[i][j]);
    }
}

// ---------------- generic 128-wide GEMM with fused epilogue ----------------
// C[row,col] = maybe_relu( A[row,:]@Bw[:,col] + bias[col] + addmat[row,col] + deg[row]*degvec[col] )
extern "C" __global__ void __launch_bounds__(256, 2)
gemm128(const float* __restrict__ A, const float* __restrict__ Bw,
        const float* __restrict__ bias, const float* __restrict__ addmat,
        const int* __restrict__ deg, const float* __restrict__ degvec,
        float* __restrict__ C, int do_relu) {
    extern __shared__ float sm[];
    float* As = sm;                // 128*PAD
    float* Bs = sm + 128 * PAD;    // 64*PAD
    int tid = threadIdx.x;
    int row0 = blockIdx.x * 128;

    load_A_transposed(A + (size_t)row0 * 128, As, tid);
    load_B_half(Bw, Bs, tid);
    __syncthreads();

    float acc[8][8];
#pragma unroll
    for (int i = 0; i < 8; i++)
#pragma unroll
        for (int j = 0; j < 8; j++) acc[i][j] = 0.f;

    int tx = tid & 15, ty = tid >> 4;
    mma_half(As, Bs, acc, ty, tx);
    __syncthreads();
    load_B_half(Bw + 64 * 128, Bs, tid);
    __syncthreads();
    mma_half(As + 64 * PAD, Bs, acc, ty, tx);

#pragma unroll
    for (int i = 0; i < 8; i++) {
        int row = row0 + ty * 8 + i;
#pragma unroll
        for (int j = 0; j < 8; j++) {
            int col = tx * 8 + j;
            float v = acc[i][j];
            if (bias)   v += bias[col];
            if (addmat) v += addmat[(size_t)row * 128 + col];
            if (deg)    v += (float)deg[row] * degvec[col];
            if (do_relu) v = fmaxf(v, 0.f);
            C[(size_t)row * 128 + col] = v;
        }
    }
}

// ---------------- per-edge kernel: distf GEMM + gather + scatter ----------------
extern "C" __global__ void __launch_bounds__(256, 2)
edge_kernel(const float* __restrict__ spos, const float* __restrict__ dpos,
            const int* __restrict__ esrc, const int* __restrict__ edst,
            const float* __restrict__ distw, const float* __restrict__ distb,
            const float* __restrict__ W1b,
            const float* __restrict__ Aproj, const float* __restrict__ Cproj,
            float* __restrict__ H, int* __restrict__ deg, int E) {
    extern __shared__ float sm[];
    float* Dst = sm;                 // distf transposed: [j=128][edge] (PAD)
    float* Bs  = sm + 128 * PAD;     // [64][PAD]
    float* dxs = Bs + 64 * PAD;
    float* dys = dxs + 128;
    float* dw0 = dys + 128;
    float* dw1 = dw0 + 128;
    float* dbv = dw1 + 128;
    int*   sidx = (int*)(dbv + 128);
    int*   didx = sidx + 128;

    int tid = threadIdx.x;
    int e0 = blockIdx.x * 128;

    if (tid < 128) {
        dw0[tid] = distw[tid];
        dw1[tid] = distw[128 + tid];
        dbv[tid] = distb[tid];
        int e = e0 + tid;
        if (e < E) {
            int s = esrc[e], d = edst[e];
            sidx[tid] = s;
            didx[tid] = d;
            float2 sp = *reinterpret_cast<const float2*>(spos + 2 * (size_t)s);
            float2 dp = *reinterpret_cast<const float2*>(dpos + 2 * (size_t)d);
            dxs[tid] = sp.x - dp.x;
            dys[tid] = sp.y - dp.y;
            atomicAdd(&deg[d], 1);
        } else {
            sidx[tid] = 0; didx[tid] = -1;
            dxs[tid] = 0.f; dys[tid] = 0.f;
        }
    }
    load_B_half(W1b, Bs, tid);
    __syncthreads();

    // distf[e][j] = relu(dx*w0[j] + dy*w1[j] + b[j]), stored transposed
    for (int i = tid; i < 128 * 128; i += 256) {
        int j = i >> 7, e = i & 127;
        Dst[j * PAD + e] =
            fmaxf(fmaf(dxs[e], dw0[j], fmaf(dys[e], dw1[j], dbv[j])), 0.f);
    }
    __syncthreads();

    float acc[8][8];
#pragma unroll
    for (int i = 0; i < 8; i++)
#pragma unroll
        for (int j = 0; j < 8; j++) acc[i][j] = 0.f;

    int tx = tid & 15, ty = tid >> 4;
    mma_half(Dst, Bs, acc, ty, tx);
    __syncthreads();
    load_B_half(W1b + 64 * 128, Bs, tid);
    __syncthreads();
    mma_half(Dst + 64 * PAD, Bs, acc, ty, tx);

    // epilogue: h = relu(acc + A[s] + C[d]); H[d] += h
#pragma unroll
    for (int i = 0; i < 8; i++) {
        int el = ty * 8 + i;
        int d = didx[el];
        if (d < 0) continue;
        const float* Ar = Aproj + (size_t)sidx[el] * 128 + tx * 8;
        const float* Cr = Cproj + (size_t)d * 128 + tx * 8;
        float* Hr = H + (size_t)d * 128 + tx * 8;
        float4 a0 = *reinterpret_cast<const float4*>(Ar);
        float4 a1 = *reinterpret_cast<const float4*>(Ar + 4);
        float4 c0 = *reinterpret_cast<const float4*>(Cr);
        float4 c1 = *reinterpret_cast<const float4*>(Cr + 4);
        float add[8] = {a0.x + c0.x, a0.y + c0.y, a0.z + c0.z, a0.w + c0.w,
                        a1.x + c1.x, a1.y + c1.y, a1.z + c1.z, a1.w + c1.w};
#pragma unroll
        for (int j = 0; j < 8; j++) {
            float v = fmaxf(acc[i][j] + add[j], 0.f);
            atomicAdd(Hr + j, v);
        }
    }
}

// ---------------- LayerNorm + ReLU (one warp per row) ----------------
extern "C" __global__ void ln_relu(const float* __restrict__ agg,
                                   const float* __restrict__ g,
                                   const float* __restrict__ b,
                                   float* __restrict__ T) {
    int gw = (blockIdx.x * blockDim.x + threadIdx.x) >> 5;
    int lane = threadIdx.x & 31;
    if (gw >= D_N) return;
    float4 x = reinterpret_cast<const float4*>(agg + (size_t)gw * 128)[lane];
    float s = x.x + x.y + x.z + x.w;
#pragma unroll
    for (int o = 16; o > 0; o >>= 1) s += __shfl_xor_sync(0xffffffffu, s, o);
    float mu = s * (1.f / 128.f);
    float d0 = x.x - mu, d1 = x.y - mu, d2 = x.z - mu, d3 = x.w - mu;
    float q = d0 * d0 + d1 * d1 + d2 * d2 + d3 * d3;
#pragma unroll
    for (int o = 16; o > 0; o >>= 1) q += __shfl_xor_sync(0xffffffffu, q, o);
    float r = rsqrtf(q * (1.f / 128.f) + 1e-5f);
    float4 gg = reinterpret_cast<const float4*>(g)[lane];
    float4 bb = reinterpret_cast<const float4*>(b)[lane];
    float4 y;
    y.x = fmaxf(fmaf(d0 * r, gg.x, bb.x), 0.f);
    y.y = fmaxf(fmaf(d1 * r, gg.y, bb.y), 0.f);
    y.z = fmaxf(fmaf(d2 * r, gg.z, bb.z), 0.f);
    y.w = fmaxf(fmaf(d3 * r, gg.w, bb.w), 0.f);
    reinterpret_cast<float4*>(T + (size_t)gw * 128)[lane] = y;
}

// ---------------- launch ----------------
extern "C" void kernel_launch(void* const* d_in, const int* in_sizes, int n_in,
                              void* d_out, int out_size) {
    const float* srcF   = (const float*)d_in[0];
    const float* spos   = (const float*)d_in[1];
    const float* dstF   = (const float*)d_in[2];
    const float* dpos   = (const float*)d_in[3];
    const float* src_w  = (const float*)d_in[4];
    const float* src_b  = (const float*)d_in[5];
    const float* dst_w  = (const float*)d_in[6];
    const float* dst_b  = (const float*)d_in[7];
    const float* dist_w = (const float*)d_in[8];
    const float* dist_b = (const float*)d_in[9];
    const float* w1     = (const float*)d_in[10];
    const float* b1     = (const float*)d_in[11];
    const float* w2     = (const float*)d_in[12];
    const float* b2     = (const float*)d_in[13];
    const float* lng    = (const float*)d_in[14];
    const float* lnb    = (const float*)d_in[15];
    const float* out_w  = (const float*)d_in[16];
    const float* out_b  = (const float*)d_in[17];
    const int*   esrc   = (const int*)d_in[18];
    const int*   edst   = (const int*)d_in[19];
    int E = in_sizes[18];
    float* out = (float*)d_out;

    float *pSrcEnc, *pDstEnc, *pA, *pC, *pH, *pAgg, *pT;
    int* pDeg;
    cudaGetSymbolAddress((void**)&pSrcEnc, g_src_enc);
    cudaGetSymbolAddress((void**)&pDstEnc, g_dst_enc);
    cudaGetSymbolAddress((void**)&pA, g_Aproj);
    cudaGetSymbolAddress((void**)&pC, g_Cproj);
    cudaGetSymbolAddress((void**)&pH, g_H);
    cudaGetSymbolAddress((void**)&pAgg, g_agg);
    cudaGetSymbolAddress((void**)&pT, g_T);
    cudaGetSymbolAddress((void**)&pDeg, g_deg);

    const int SMEM_G = (128 * PAD + 64 * PAD) * 4;           // 101376 B
    const int SMEM_E = SMEM_G + 7 * 128 * 4;                 // +3584 B
    cudaFuncSetAttribute(gemm128, cudaFuncAttributeMaxDynamicSharedMemorySize, SMEM_E);
    cudaFuncSetAttribute(edge_kernel, cudaFuncAttributeMaxDynamicSharedMemorySize, SMEM_E);

    cudaMemsetAsync(pH, 0, (size_t)D_N * F * sizeof(float));
    cudaMemsetAsync(pDeg, 0, (size_t)D_N * sizeof(int));

    // node encoders + per-node W1 projections
    gemm128<<<128, 256, SMEM_G>>>(srcF, src_w, src_b, nullptr, nullptr, nullptr, pSrcEnc, 1);
    gemm128<<<128, 256, SMEM_G>>>(pSrcEnc, w1, nullptr, nullptr, nullptr, nullptr, pA, 0);
    gemm128<<<128, 256, SMEM_G>>>(dstF, dst_w, dst_b, nullptr, nullptr, nullptr, pDstEnc, 1);
    gemm128<<<128, 256, SMEM_G>>>(pDstEnc, w1 + 256 * 128, b1, nullptr, nullptr, nullptr, pC, 0);

    // per-edge hidden + scatter
    int nb = (E + 127) / 128;
    edge_kernel<<<nb, 256, SMEM_E>>>(spos, dpos, esrc, edst, dist_w, dist_b,
                                     w1 + 128 * 128, pA, pC, pH, pDeg, E);

    // agg = dst_enc + H@W2 + deg*b2 ; LN+relu ; out = relu(T@out_w + out_b + dstF)
    gemm128<<<128, 256, SMEM_G>>>(pH, w2, nullptr, pDstEnc, pDeg, b2, pAgg, 0);
    ln_relu<<<D_N / 8, 256>>>(pAgg, lng, lnb, pT);
    gemm128<<<128, 256, SMEM_G>>>(pT, out_w, out_b, dstF, nullptr, nullptr, out, 1);
}

// round 3
// speedup vs baseline: 1.0076x; 1.0076x over previous
#include <cuda_runtime.h>

// GraphAttention restructured:
//   A  = relu(srcF@src_w+src_b) @ W1[0:128]                (per src node)
//   C  = relu(dstF@dst_w+dst_b) @ W1[256:384] + b1         (per dst node)
//   per edge e=(s,d): distf = relu(dpos@dist_w + dist_b)
//                     h = relu(A[s] + distf@W1[128:256] + C[d]); H[d] += h; deg[d]++
//   agg = dst_enc + H@W2 + deg*b2 ; T = relu(LN(agg))
//   out = relu(T@out_w + out_b + dstF)

#define S_N 16384
#define D_N 16384
#define F   128
#define PAD 132   // 132 floats = 528B, 16B-aligned rows

__device__ float g_src_enc[S_N * F];
__device__ float g_dst_enc[D_N * F];
__device__ float g_Aproj[S_N * F];
__device__ float g_Cproj[D_N * F];
__device__ float g_H[D_N * F];
__device__ float g_agg[D_N * F];
__device__ float g_T[D_N * F];
__device__ int   g_deg[D_N];

// ---------------- shared-tile helpers ----------------

// A row-major [128 x 128] -> As[k*PAD + row] (transposed, k-major)
__device__ __forceinline__ void load_A_transposed(const float* __restrict__ A,
                                                  float* As, int tid) {
    for (int c = tid; c < 128 * 32; c += 256) {
        int kq = c & 31, row = c >> 5;
        float4 v = *reinterpret_cast<const float4*>(A + (size_t)row * 128 + kq * 4);
        As[(kq * 4 + 0) * PAD + row] = v.x;
        As[(kq * 4 + 1) * PAD + row] = v.y;
        As[(kq * 4 + 2) * PAD + row] = v.z;
        As[(kq * 4 + 3) * PAD + row] = v.w;
    }
}

// B rows [64 x 128] row-major -> Bs[k*PAD + col]
__device__ __forceinline__ void load_B_half(const float* __restrict__ B,
                                            float* Bs, int tid) {
    for (int c = tid; c < 64 * 32; c += 256) {
        int colq = c & 31, k = c >> 5;
        *reinterpret_cast<float4*>(Bs + k * PAD + colq * 4) =
            *reinterpret_cast<const float4*>(B + (size_t)k * 128 + colq * 4);
    }
}

// 64-step K loop: acc[8][8] += As[k][ty*8+i] * Bs[k][tx*8+j]
__device__ __forceinline__ void mma_half(const float* __restrict__ As,
                                         const float* __restrict__ Bs,
                                         float acc[8][8], int ty, int tx) {
#pragma unroll 8
    for (int k = 0; k < 64; k++) {
        float4 a0 = *reinterpret_cast<const float4*>(As + k * PAD + ty * 8);
        float4 a1 = *reinterpret_cast<const float4*>(As + k * PAD + ty * 8 + 4);
        float4 b0 = *reinterpret_cast<const float4*>(Bs + k * PAD + tx * 8);
        float4 b1 = *reinterpret_cast<const float4*>(Bs + k * PAD + tx * 8 + 4);
        float a[8] = {a0.x, a0.y, a0.z, a0.w, a1.x, a1.y, a1.z, a1.w};
        float b[8] = {b0.x, b0.y, b0.z, b0.w, b1.x, b1.y, b1.z, b1.w};
#pragma unroll
        for (int i = 0; i < 8; i++)
#pragma unroll
            for (int j = 0; j < 8; j++)
                acc[i][j] = fmaf(a[i], b[j], acc[i][j]);
    }
}

// ---------------- generic 128-wide GEMM with fused epilogue ----------------
// C[row,col] = maybe_relu( A[row,:]@Bw[:,col] + bias[col] + addmat[row,col] + deg[row]*degvec[col] )
extern "C" __global__ void __launch_bounds__(256, 2)
gemm128(const float* __restrict__ A, const float* __restrict__ Bw,
        const float* __restrict__ bias, const float* __restrict__ addmat,
        const int* __restrict__ deg, const float* __restrict__ degvec,
        float* __restrict__ C, int do_relu) {
    extern __shared__ float sm[];
    float* As = sm;                // 128*PAD
    float* Bs = sm + 128 * PAD;    // 64*PAD
    int tid = threadIdx.x;
    int row0 = blockIdx.x * 128;

    load_A_transposed(A + (size_t)row0 * 128, As, tid);
    load_B_half(Bw, Bs, tid);
    __syncthreads();

    float acc[8][8];
#pragma unroll
    for (int i = 0; i < 8; i++)
#pragma unroll
        for (int j = 0; j < 8; j++) acc[i][j] = 0.f;

    int tx = tid & 15, ty = tid >> 4;
    mma_half(As, Bs, acc, ty, tx);
    __syncthreads();
    load_B_half(Bw + 64 * 128, Bs, tid);
    __syncthreads();
    mma_half(As + 64 * PAD, Bs, acc, ty, tx);

#pragma unroll
    for (int i = 0; i < 8; i++) {
        int row = row0 + ty * 8 + i;
#pragma unroll
        for (int j = 0; j < 8; j++) {
            int col = tx * 8 + j;
            float v = acc[i][j];
            if (bias)   v += bias[col];
            if (addmat) v += addmat[(size_t)row * 128 + col];
            if (deg)    v += (float)deg[row] * degvec[col];
            if (do_relu) v = fmaxf(v, 0.f);
            C[(size_t)row * 128 + col] = v;
        }
    }
}

// ---------------- per-edge kernel: distf GEMM + gather + scatter ----------------
extern "C" __global__ void __launch_bounds__(256, 2)
edge_kernel(const float* __restrict__ spos, const float* __restrict__ dpos,
            const int* __restrict__ esrc, const int* __restrict__ edst,
            const float* __restrict__ distw, const float* __restrict__ distb,
            const float* __restrict__ W1b,
            const float* __restrict__ Aproj, const float* __restrict__ Cproj,
            float* __restrict__ H, int* __restrict__ deg, int E) {
    extern __shared__ float sm[];
    float* Dst = sm;                 // distf transposed: [j=128][edge] (PAD)
    float* Bs  = sm + 128 * PAD;     // [64][PAD]
    float* dxs = Bs + 64 * PAD;
    float* dys = dxs + 128;
    float* dw0 = dys + 128;
    float* dw1 = dw0 + 128;
    float* dbv = dw1 + 128;
    int*   sidx = (int*)(dbv + 128);
    int*   didx = sidx + 128;

    int tid = threadIdx.x;
    int e0 = blockIdx.x * 128;

    if (tid < 128) {
        dw0[tid] = distw[tid];
        dw1[tid] = distw[128 + tid];
        dbv[tid] = distb[tid];
        int e = e0 + tid;
        if (e < E) {
            int s = esrc[e], d = edst[e];
            sidx[tid] = s;
            didx[tid] = d;
            float2 sp = *reinterpret_cast<const float2*>(spos + 2 * (size_t)s);
            float2 dp = *reinterpret_cast<const float2*>(dpos + 2 * (size_t)d);
            dxs[tid] = sp.x - dp.x;
            dys[tid] = sp.y - dp.y;
            atomicAdd(&deg[d], 1);
        } else {
            sidx[tid] = 0; didx[tid] = -1;
            dxs[tid] = 0.f; dys[tid] = 0.f;
        }
    }
    load_B_half(W1b, Bs, tid);
    __syncthreads();

    // distf[e][j] = relu(dx*w0[j] + dy*w1[j] + b[j]), stored transposed
    for (int i = tid; i < 128 * 128; i += 256) {
        int j = i >> 7, e = i & 127;
        Dst[j * PAD + e] =
            fmaxf(fmaf(dxs[e], dw0[j], fmaf(dys[e], dw1[j], dbv[j])), 0.f);
    }
    __syncthreads();

    float acc[8][8];
#pragma unroll
    for (int i = 0; i < 8; i++)
#pragma unroll
        for (int j = 0; j < 8; j++) acc[i][j] = 0.f;

    int tx = tid & 15, ty = tid >> 4;
    mma_half(Dst, Bs, acc, ty, tx);
    __syncthreads();
    load_B_half(W1b + 64 * 128, Bs, tid);
    __syncthreads();
    mma_half(Dst + 64 * PAD, Bs, acc, ty, tx);

    // epilogue: h = relu(acc + A[s] + C[d]); H[d] += h
#pragma unroll
    for (int i = 0; i < 8; i++) {
        int el = ty * 8 + i;
        int d = didx[el];
        if (d < 0) continue;
        const float* Ar = Aproj + (size_t)sidx[el] * 128 + tx * 8;
        const float* Cr = Cproj + (size_t)d * 128 + tx * 8;
        float* Hr = H + (size_t)d * 128 + tx * 8;
        float4 a0 = *reinterpret_cast<const float4*>(Ar);
        float4 a1 = *reinterpret_cast<const float4*>(Ar + 4);
        float4 c0 = *reinterpret_cast<const float4*>(Cr);
        float4 c1 = *reinterpret_cast<const float4*>(Cr + 4);
        float add[8] = {a0.x + c0.x, a0.y + c0.y, a0.z + c0.z, a0.w + c0.w,
                        a1.x + c1.x, a1.y + c1.y, a1.z + c1.z, a1.w + c1.w};
#pragma unroll
        for (int j = 0; j < 8; j++) {
            float v = fmaxf(acc[i][j] + add[j], 0.f);
            atomicAdd(Hr + j, v);
        }
    }
}

// ---------------- LayerNorm + ReLU (one warp per row) ----------------
extern "C" __global__ void ln_relu(const float* __restrict__ agg,
                                   const float* __restrict__ g,
                                   const float* __restrict__ b,
                                   float* __restrict__ T) {
    int gw = (blockIdx.x * blockDim.x + threadIdx.x) >> 5;
    int lane = threadIdx.x & 31;
    if (gw >= D_N) return;
    float4 x = reinterpret_cast<const float4*>(agg + (size_t)gw * 128)[lane];
    float s = x.x + x.y + x.z + x.w;
#pragma unroll
    for (int o = 16; o > 0; o >>= 1) s += __shfl_xor_sync(0xffffffffu, s, o);
    float mu = s * (1.f / 128.f);
    float d0 = x.x - mu, d1 = x.y - mu, d2 = x.z - mu, d3 = x.w - mu;
    float q = d0 * d0 + d1 * d1 + d2 * d2 + d3 * d3;
#pragma unroll
    for (int o = 16; o > 0; o >>= 1) q += __shfl_xor_sync(0xffffffffu, q, o);
    float r = rsqrtf(q * (1.f / 128.f) + 1e-5f);
    float4 gg = reinterpret_cast<const float4*>(g)[lane];
    float4 bb = reinterpret_cast<const float4*>(b)[lane];
    float4 y;
    y.x = fmaxf(fmaf(d0 * r, gg.x, bb.x), 0.f);
    y.y = fmaxf(fmaf(d1 * r, gg.y, bb.y), 0.f);
    y.z = fmaxf(fmaf(d2 * r, gg.z, bb.z), 0.f);
    y.w = fmaxf(fmaf(d3 * r, gg.w, bb.w), 0.f);
    reinterpret_cast<float4*>(T + (size_t)gw * 128)[lane] = y;
}

// ---------------- launch ----------------
extern "C" void kernel_launch(void* const* d_in, const int* in_sizes, int n_in,
                              void* d_out, int out_size) {
    const float* srcF   = (const float*)d_in[0];
    const float* spos   = (const float*)d_in[1];
    const float* dstF   = (const float*)d_in[2];
    const float* dpos   = (const float*)d_in[3];
    const float* src_w  = (const float*)d_in[4];
    const float* src_b  = (const float*)d_in[5];
    const float* dst_w  = (const float*)d_in[6];
    const float* dst_b  = (const float*)d_in[7];
    const float* dist_w = (const float*)d_in[8];
    const float* dist_b = (const float*)d_in[9];
    const float* w1     = (const float*)d_in[10];
    const float* b1     = (const float*)d_in[11];
    const float* w2     = (const float*)d_in[12];
    const float* b2     = (const float*)d_in[13];
    const float* lng    = (const float*)d_in[14];
    const float* lnb    = (const float*)d_in[15];
    const float* out_w  = (const float*)d_in[16];
    const float* out_b  = (const float*)d_in[17];
    const int*   esrc   = (const int*)d_in[18];
    const int*   edst   = (const int*)d_in[19];
    int E = in_sizes[18];
    float* out = (float*)d_out;

    float *pSrcEnc, *pDstEnc, *pA, *pC, *pH, *pAgg, *pT;
    int* pDeg;
    cudaGetSymbolAddress((void**)&pSrcEnc, g_src_enc);
    cudaGetSymbolAddress((void**)&pDstEnc, g_dst_enc);
    cudaGetSymbolAddress((void**)&pA, g_Aproj);
    cudaGetSymbolAddress((void**)&pC, g_Cproj);
    cudaGetSymbolAddress((void**)&pH, g_H);
    cudaGetSymbolAddress((void**)&pAgg, g_agg);
    cudaGetSymbolAddress((void**)&pT, g_T);
    cudaGetSymbolAddress((void**)&pDeg, g_deg);

    const int SMEM_G = (128 * PAD + 64 * PAD) * 4;           // 101376 B
    const int SMEM_E = SMEM_G + 7 * 128 * 4;                 // +3584 B
    cudaFuncSetAttribute(gemm128, cudaFuncAttributeMaxDynamicSharedMemorySize, SMEM_E);
    cudaFuncSetAttribute(edge_kernel, cudaFuncAttributeMaxDynamicSharedMemorySize, SMEM_E);

    cudaMemsetAsync(pH, 0, (size_t)D_N * F * sizeof(float));
    cudaMemsetAsync(pDeg, 0, (size_t)D_N * sizeof(int));

    // node encoders + per-node W1 projections
    gemm128<<<128, 256, SMEM_G>>>(srcF, src_w, src_b, nullptr, nullptr, nullptr, pSrcEnc, 1);
    gemm128<<<128, 256, SMEM_G>>>(pSrcEnc, w1, nullptr, nullptr, nullptr, nullptr, pA, 0);
    gemm128<<<128, 256, SMEM_G>>>(dstF, dst_w, dst_b, nullptr, nullptr, nullptr, pDstEnc, 1);
    gemm128<<<128, 256, SMEM_G>>>(pDstEnc, w1 + 256 * 128, b1, nullptr, nullptr, nullptr, pC, 0);

    // per-edge hidden + scatter
    int nb = (E + 127) / 128;
    edge_kernel<<<nb, 256, SMEM_E>>>(spos, dpos, esrc, edst, dist_w, dist_b,
                                     w1 + 128 * 128, pA, pC, pH, pDeg, E);

    // agg = dst_enc + H@W2 + deg*b2 ; LN+relu ; out = relu(T@out_w + out_b + dstF)
    gemm128<<<128, 256, SMEM_G>>>(pH, w2, nullptr, pDstEnc, pDeg, b2, pAgg, 0);
    ln_relu<<<D_N / 8, 256>>>(pAgg, lng, lnb, pT);
    gemm128<<<128, 256, SMEM_G>>>(pT, out_w, out_b, dstF, nullptr, nullptr, out, 1);
}